// round 2
// baseline (speedup 1.0000x reference)
#include <cuda_runtime.h>
#include <math.h>

#define NN 20000
#define NE 640000
#define D  128
#define TE 32
#define TN 32

// ---------------- scratch (static device memory; no allocations) ----------------
__device__ float g_hh[NN * D];      // h @ W_lin + b (pre-LN node features)
__device__ float g_agg[NN * D];     // segment-sum of messages
__device__ float g_aggx[NN * 3];    // segment-sum of coord updates
__device__ float g_e3[NE * 3];      // [dist, edge_attr, geo] per edge
__device__ float g_Wa1p[260 * D];   // Wa1 padded 259->260 rows
__device__ float g_We1p[132 * D];   // We1 padded 131->132 rows
__device__ float g_Wc1p[260 * D];   // Wc1 padded 259->260 rows

__device__ __forceinline__ float siluf(float v) { return v / (1.f + expf(-v)); }

// ---------------- weight pad-copy (rows K..Kpad-1 zeroed) ----------------
__global__ void prep_weights(const float* __restrict__ Wa1,
                             const float* __restrict__ We1,
                             const float* __restrict__ Wc1) {
    int m = blockIdx.y;
    const float* src; float* dst; int K, Kp;
    if (m == 0)      { src = Wa1; dst = g_Wa1p; K = 259; Kp = 260; }
    else if (m == 1) { src = We1; dst = g_We1p; K = 131; Kp = 132; }
    else             { src = Wc1; dst = g_Wc1p; K = 259; Kp = 260; }
    int total = Kp * D;
    for (int idx = blockIdx.x * blockDim.x + threadIdx.x; idx < total;
         idx += gridDim.x * blockDim.x) {
        int k = idx / D;
        dst[idx] = (k < K) ? src[idx] : 0.f;
    }
}

__global__ void zero_scratch() {
    int idx = blockIdx.x * blockDim.x + threadIdx.x;
    int stride = gridDim.x * blockDim.x;
    for (int i = idx; i < NN * D; i += stride) g_agg[i] = 0.f;
    for (int i = idx; i < NN * 3; i += stride) g_aggx[i] = 0.f;
}

// ---------------- shared FFMA "GEMM" core ----------------
// Thread d computes out[e][d] for e in [0,TEc). Input rows in SMEM (stride LD,
// 16B aligned), weights W[k*D+d] streamed coalesced from global (L1/L2 hit).
template <int TEc, int K, int LD>
__device__ __forceinline__ void mlp_layer(const float* __restrict__ W,
                                          const float* s_in, float bias,
                                          float* acc, int d) {
#pragma unroll
    for (int e = 0; e < TEc; e++) acc[e] = bias;
#pragma unroll 2
    for (int k = 0; k < K; k += 4) {
        float w0 = W[(k + 0) * D + d];
        float w1 = W[(k + 1) * D + d];
        float w2 = W[(k + 2) * D + d];
        float w3 = W[(k + 3) * D + d];
#pragma unroll
        for (int e = 0; e < TEc; e++) {
            float4 v = *(const float4*)(s_in + e * LD + k);
            acc[e] = fmaf(v.x, w0, acc[e]);
            acc[e] = fmaf(v.y, w1, acc[e]);
            acc[e] = fmaf(v.z, w2, acc[e]);
            acc[e] = fmaf(v.w, w3, acc[e]);
        }
    }
}

// ---------------- node linear: g_hh = h @ W_lin + b ----------------
__global__ void node_lin(const float* __restrict__ h,
                         const float* __restrict__ Wlin,
                         const float* __restrict__ blin) {
    __shared__ __align__(16) float s_in[TN * D];
    int t = threadIdx.x;
    int r0 = blockIdx.x * TN;
    for (int e = 0; e < TN; e++) s_in[e * D + t] = h[(r0 + e) * D + t];
    __syncthreads();
    float acc[TN];
    mlp_layer<TN, 128, 128>(Wlin, s_in, blin[t], acc, t);
#pragma unroll
    for (int e = 0; e < TN; e++) g_hh[(r0 + e) * D + t] = acc[e];
}

// ---------------- edge message + attention kernel ----------------
__global__ void edge_msg(const float* __restrict__ x, const int* __restrict__ ei,
                         const float* __restrict__ edge_mask,
                         const float* __restrict__ edge_attr,
                         const float* __restrict__ We2,
                         const float* __restrict__ be1,
                         const float* __restrict__ be2,
                         const float* __restrict__ ba1,
                         const float* __restrict__ Wa2,
                         const float* __restrict__ ba2) {
    extern __shared__ float sm[];
    float* s_att_in = sm;                    // TE*260  [hr | hc | e3 | 0]
    float* s_msg    = s_att_in + TE * 260;   // TE*132  [hc-hr | e3 | 0]
    float* s_m1     = s_msg + TE * 132;      // TE*128  layer-1 output
    float* s_w2     = s_m1 + TE * 128;       // 128     Wa2
    float* s_att    = s_w2 + 128;            // TE
    float* s_em     = s_att + TE;            // TE
    float* s_gp     = s_em + TE;             // TE*4    geo warp partials
    int*   s_row    = (int*)(s_gp + TE * 4); // TE
    int*   s_col    = s_row + TE;            // TE

    int t = threadIdx.x, lane = t & 31, wid = t >> 5;
    int e0 = blockIdx.x * TE;

    if (t < TE) {
        s_row[t] = ei[e0 + t];
        s_col[t] = ei[NE + e0 + t];
        s_em[t]  = edge_mask[e0 + t];
    }
    s_w2[t] = Wa2[t];
    __syncthreads();

    for (int e = 0; e < TE; e++) {
        float hr = g_hh[s_row[e] * D + t];
        float hc = g_hh[s_col[e] * D + t];
        s_att_in[e * 260 + t]       = hr;
        s_att_in[e * 260 + 128 + t] = hc;
        float v = hc - hr;
        s_msg[e * 132 + t] = v;
        float p = v * v;
#pragma unroll
        for (int o = 16; o > 0; o >>= 1) p += __shfl_down_sync(0xffffffffu, p, o);
        if (lane == 0) s_gp[e * 4 + wid] = p;
    }
    __syncthreads();

    if (t < TE) {
        int e = t;
        float geo = sqrtf(s_gp[e * 4] + s_gp[e * 4 + 1] + s_gp[e * 4 + 2] +
                          s_gp[e * 4 + 3] + 1e-8f);
        int r = s_row[e], c = s_col[e];
        float dx = x[r * 3 + 0] - x[c * 3 + 0];
        float dy = x[r * 3 + 1] - x[c * 3 + 1];
        float dz = x[r * 3 + 2] - x[c * 3 + 2];
        float dist = sqrtf(dx * dx + dy * dy + dz * dz + 1e-8f);
        float ea = edge_attr[e0 + e];
        s_att_in[e * 260 + 256] = dist;
        s_att_in[e * 260 + 257] = ea;
        s_att_in[e * 260 + 258] = geo;
        s_att_in[e * 260 + 259] = 0.f;
        s_msg[e * 132 + 128] = dist;
        s_msg[e * 132 + 129] = ea;
        s_msg[e * 132 + 130] = geo;
        s_msg[e * 132 + 131] = 0.f;
        g_e3[(e0 + e) * 3 + 0] = dist;
        g_e3[(e0 + e) * 3 + 1] = ea;
        g_e3[(e0 + e) * 3 + 2] = geo;
    }
    __syncthreads();

    float acc[TE];
    // A1 = silu(att_in @ Wa1 + ba1)
    mlp_layer<TE, 260, 260>(g_Wa1p, s_att_in, ba1[t], acc, t);
#pragma unroll
    for (int e = 0; e < TE; e++) s_m1[e * 128 + t] = siluf(acc[e]);
    __syncthreads();

    // att = sigmoid(A1 @ Wa2 + ba2) * edge_mask    (warp handles 8 edges)
    {
        float b2 = ba2[0];
        for (int i = 0; i < TE / 4; i++) {
            int e = wid * (TE / 4) + i;
            float s = s_m1[e * 128 + lane]      * s_w2[lane] +
                      s_m1[e * 128 + lane + 32] * s_w2[lane + 32] +
                      s_m1[e * 128 + lane + 64] * s_w2[lane + 64] +
                      s_m1[e * 128 + lane + 96] * s_w2[lane + 96];
#pragma unroll
            for (int o = 16; o > 0; o >>= 1) s += __shfl_down_sync(0xffffffffu, s, o);
            if (lane == 0) {
                float z = s + b2;
                s_att[e] = s_em[e] / (1.f + expf(-z));
            }
        }
    }
    __syncthreads();

    // M1 = silu(msg_in @ We1 + be1)
    mlp_layer<TE, 132, 132>(g_We1p, s_msg, be1[t], acc, t);
#pragma unroll
    for (int e = 0; e < TE; e++) s_m1[e * 128 + t] = siluf(acc[e]);
    __syncthreads();

    // msg = (M1 @ We2 + be2) * att ; scatter to agg[row]
    mlp_layer<TE, 128, 128>(We2, s_m1, be2[t], acc, t);
#pragma unroll
    for (int e = 0; e < TE; e++) {
        float m = acc[e] * s_att[e];
        atomicAdd(&g_agg[s_row[e] * D + t], m);
    }
}

// ---------------- node MLP + residual + LayerNorm + silu -> d_out ----------------
__global__ void node_mlp(const float* __restrict__ Wn1, const float* __restrict__ bn1,
                         const float* __restrict__ Wn2, const float* __restrict__ bn2,
                         const float* __restrict__ ln_g, const float* __restrict__ ln_b,
                         float* __restrict__ out_h) {
    __shared__ __align__(16) float s_a[TN * 128];
    __shared__ __align__(16) float s_t[TN * 128];
    __shared__ float s_mu[TN], s_rs[TN];
    int t = threadIdx.x, lane = t & 31, wid = t >> 5;
    int r0 = blockIdx.x * TN;

    for (int e = 0; e < TN; e++) s_a[e * 128 + t] = g_agg[(r0 + e) * D + t];
    __syncthreads();

    float acc[TN];
    mlp_layer<TN, 128, 128>(Wn1, s_a, bn1[t], acc, t);
#pragma unroll
    for (int e = 0; e < TN; e++) s_t[e * 128 + t] = siluf(acc[e]);
    __syncthreads();

    mlp_layer<TN, 128, 128>(Wn2, s_t, bn2[t], acc, t);
#pragma unroll
    for (int e = 0; e < TN; e++) {
        float v = g_hh[(r0 + e) * D + t] + acc[e];
        s_a[e * 128 + t] = v;  // overwrite (safe: all s_a reads done pre-sync)
    }
    __syncthreads();

    // LayerNorm stats: warp handles 8 rows
    for (int i = 0; i < TN / 4; i++) {
        int e = wid * (TN / 4) + i;
        float v0 = s_a[e * 128 + lane];
        float v1 = s_a[e * 128 + lane + 32];
        float v2 = s_a[e * 128 + lane + 64];
        float v3 = s_a[e * 128 + lane + 96];
        float s = v0 + v1 + v2 + v3;
        float q = v0 * v0 + v1 * v1 + v2 * v2 + v3 * v3;
#pragma unroll
        for (int o = 16; o > 0; o >>= 1) {
            s += __shfl_down_sync(0xffffffffu, s, o);
            q += __shfl_down_sync(0xffffffffu, q, o);
        }
        if (lane == 0) {
            float mu = s * (1.f / 128.f);
            float var = q * (1.f / 128.f) - mu * mu;
            s_mu[e] = mu;
            s_rs[e] = rsqrtf(var + 1e-5f);
        }
    }
    __syncthreads();

    float g = ln_g[t], bb = ln_b[t];
    for (int e = 0; e < TN; e++) {
        float v = (s_a[e * 128 + t] - s_mu[e]) * s_rs[e] * g + bb;
        out_h[(r0 + e) * D + t] = siluf(v);
    }
}

// ---------------- coord MLP + scatter ----------------
__global__ void edge_coord(const float* __restrict__ x, const int* __restrict__ ei,
                           const float* __restrict__ edge_mask,
                           const float* __restrict__ hh2,  // = d_out[0:N*D]
                           const float* __restrict__ bc1,
                           const float* __restrict__ Wc2,
                           const float* __restrict__ bc2,
                           const float* __restrict__ Wc3) {
    extern __shared__ float sm[];
    float* s_in = sm;                     // TE*260  [h2r | h2c | e3 | 0]; cols 0..127 reused for m2
    float* s_m1 = s_in + TE * 260;        // TE*128
    float* s_w3 = s_m1 + TE * 128;        // 128
    float* s_mm = s_w3 + 128;             // TE (m * edge_mask)
    float* s_em = s_mm + TE;              // TE
    int*   s_row = (int*)(s_em + TE);
    int*   s_col = s_row + TE;

    int t = threadIdx.x, lane = t & 31, wid = t >> 5;
    int e0 = blockIdx.x * TE;

    if (t < TE) {
        s_row[t] = ei[e0 + t];
        s_col[t] = ei[NE + e0 + t];
        s_em[t]  = edge_mask[e0 + t];
    }
    s_w3[t] = Wc3[t];
    __syncthreads();

    for (int e = 0; e < TE; e++) {
        s_in[e * 260 + t]       = hh2[s_row[e] * D + t];
        s_in[e * 260 + 128 + t] = hh2[s_col[e] * D + t];
    }
    if (t < TE) {
        int e = t;
        s_in[e * 260 + 256] = g_e3[(e0 + e) * 3 + 0];
        s_in[e * 260 + 257] = g_e3[(e0 + e) * 3 + 1];
        s_in[e * 260 + 258] = g_e3[(e0 + e) * 3 + 2];
        s_in[e * 260 + 259] = 0.f;
    }
    __syncthreads();

    float acc[TE];
    mlp_layer<TE, 260, 260>(g_Wc1p, s_in, bc1[t], acc, t);
#pragma unroll
    for (int e = 0; e < TE; e++) s_m1[e * 128 + t] = siluf(acc[e]);
    __syncthreads();

    mlp_layer<TE, 128, 128>(Wc2, s_m1, bc2[t], acc, t);
#pragma unroll
    for (int e = 0; e < TE; e++) s_in[e * 260 + t] = siluf(acc[e]);  // m2 -> cols 0..127
    __syncthreads();

    // m = m2 @ Wc3 (no bias); trans scatter
    for (int i = 0; i < TE / 4; i++) {
        int e = wid * (TE / 4) + i;
        float s = s_in[e * 260 + lane]      * s_w3[lane] +
                  s_in[e * 260 + lane + 32] * s_w3[lane + 32] +
                  s_in[e * 260 + lane + 64] * s_w3[lane + 64] +
                  s_in[e * 260 + lane + 96] * s_w3[lane + 96];
#pragma unroll
        for (int o = 16; o > 0; o >>= 1) s += __shfl_down_sync(0xffffffffu, s, o);
        if (lane == 0) s_mm[e] = s * s_em[e];
    }
    __syncthreads();

    if (t < TE) {
        int e = t;
        int r = s_row[e], c = s_col[e];
        float dx = x[r * 3 + 0] - x[c * 3 + 0];
        float dy = x[r * 3 + 1] - x[c * 3 + 1];
        float dz = x[r * 3 + 2] - x[c * 3 + 2];
        float dist = s_in[e * 260 + 256];  // cols 256.. untouched by m2 overwrite
        float inv = 1.f / (dist + 1.f);
        float m = s_mm[e];
        atomicAdd(&g_aggx[r * 3 + 0], dx * inv * m);
        atomicAdd(&g_aggx[r * 3 + 1], dy * inv * m);
        atomicAdd(&g_aggx[r * 3 + 2], dz * inv * m);
    }
}

__global__ void finalize_x(const float* __restrict__ x,
                           const float* __restrict__ node_mask,
                           float* __restrict__ out) {
    int i = blockIdx.x * blockDim.x + threadIdx.x;
    if (i < NN * 3) {
        out[i] = (x[i] + g_aggx[i] * (1.f / 100.f)) * node_mask[i / 3];
    }
}

// ---------------- launcher ----------------
extern "C" void kernel_launch(void* const* d_in, const int* in_sizes, int n_in,
                              void* d_out, int out_size) {
    const float* h         = (const float*)d_in[0];
    const float* x         = (const float*)d_in[1];
    const int*   ei        = (const int*)d_in[2];
    const float* node_mask = (const float*)d_in[3];
    const float* edge_mask = (const float*)d_in[4];
    const float* edge_attr = (const float*)d_in[5];
    const float* Wlin = (const float*)d_in[6];
    const float* blin = (const float*)d_in[7];
    const float* We1  = (const float*)d_in[8];
    const float* be1  = (const float*)d_in[9];
    const float* We2  = (const float*)d_in[10];
    const float* be2  = (const float*)d_in[11];
    const float* Wn1  = (const float*)d_in[12];
    const float* bn1  = (const float*)d_in[13];
    const float* Wn2  = (const float*)d_in[14];
    const float* bn2  = (const float*)d_in[15];
    const float* Wa1  = (const float*)d_in[16];
    const float* ba1  = (const float*)d_in[17];
    const float* Wa2  = (const float*)d_in[18];
    const float* ba2  = (const float*)d_in[19];
    const float* ln_g = (const float*)d_in[20];
    const float* ln_b = (const float*)d_in[21];
    const float* Wc1  = (const float*)d_in[22];
    const float* bc1  = (const float*)d_in[23];
    const float* Wc2  = (const float*)d_in[24];
    const float* bc2  = (const float*)d_in[25];
    const float* Wc3  = (const float*)d_in[26];
    float* out = (float*)d_out;

    const int SMEM_MSG = (TE * 260 + TE * 132 + TE * 128 + 128 + TE + TE + TE * 4) * 4
                         + 2 * TE * 4;
    const int SMEM_CRD = (TE * 260 + TE * 128 + 128 + TE + TE) * 4 + 2 * TE * 4;

    cudaFuncSetAttribute(edge_msg, cudaFuncAttributeMaxDynamicSharedMemorySize, SMEM_MSG);
    cudaFuncSetAttribute(edge_coord, cudaFuncAttributeMaxDynamicSharedMemorySize, SMEM_CRD);

    prep_weights<<<dim3(131, 3), 256>>>(Wa1, We1, Wc1);
    zero_scratch<<<1024, 256>>>();
    node_lin<<<NN / TN, 128>>>(h, Wlin, blin);
    edge_msg<<<NE / TE, 128, SMEM_MSG>>>(x, ei, edge_mask, edge_attr,
                                         We2, be1, be2, ba1, Wa2, ba2);
    node_mlp<<<NN / TN, 128>>>(Wn1, bn1, Wn2, bn2, ln_g, ln_b, out);
    edge_coord<<<NE / TE, 128, SMEM_CRD>>>(x, ei, edge_mask, out, bc1, Wc2, bc2, Wc3);
    finalize_x<<<(NN * 3 + 255) / 256, 256>>>(x, node_mask, out + NN * D);
}

// round 3
// speedup vs baseline: 1.0263x; 1.0263x over previous
#include <cuda_runtime.h>
#include <math.h>

#define NN 20000
#define NE 640000
#define D  128
#define TE 32
#define TN 32
#define LDE 36   // edge-dim stride: 36*4=144B -> 16B-aligned rows, 4-way STS conflict only

typedef unsigned long long u64;

// ---------------- scratch (static device memory; no allocations) ----------------
__device__ float g_hh[NN * D];      // h @ W_lin + b (pre-LN node features)
__device__ float g_agg[NN * D];     // segment-sum of messages
__device__ float g_aggx[NN * 3];    // segment-sum of coord updates
__device__ float g_e3[NE * 3];      // [dist, edge_attr, geo] per edge
__device__ float g_Wa1p[260 * D];   // Wa1 padded 259->260 rows
__device__ float g_We1p[132 * D];   // We1 padded 131->132 rows
__device__ float g_Wc1p[260 * D];   // Wc1 padded 259->260 rows

__device__ __forceinline__ float siluf(float v) { return v / (1.f + expf(-v)); }

// ---------------- packed f32x2 primitives ----------------
__device__ __forceinline__ u64 ffma2(u64 a, u64 b, u64 c) {
    u64 d;
    asm("fma.rn.f32x2 %0, %1, %2, %3;" : "=l"(d) : "l"(a), "l"(b), "l"(c));
    return d;
}
__device__ __forceinline__ u64 dup2(float w) {
    u64 d;
    asm("mov.b64 %0, {%1, %1};" : "=l"(d) : "f"(w));
    return d;
}
__device__ __forceinline__ float2 unpk(u64 a) {
    float2 r;
    asm("mov.b64 {%0, %1}, %2;" : "=f"(r.x), "=f"(r.y) : "l"(a));
    return r;
}

// ---------------- weight pad-copy (rows K..Kpad-1 zeroed) ----------------
__global__ void prep_weights(const float* __restrict__ Wa1,
                             const float* __restrict__ We1,
                             const float* __restrict__ Wc1) {
    int m = blockIdx.y;
    const float* src; float* dst; int K, Kp;
    if (m == 0)      { src = Wa1; dst = g_Wa1p; K = 259; Kp = 260; }
    else if (m == 1) { src = We1; dst = g_We1p; K = 131; Kp = 132; }
    else             { src = Wc1; dst = g_Wc1p; K = 259; Kp = 260; }
    int total = Kp * D;
    for (int idx = blockIdx.x * blockDim.x + threadIdx.x; idx < total;
         idx += gridDim.x * blockDim.x) {
        int k = idx / D;
        dst[idx] = (k < K) ? src[idx] : 0.f;
    }
}

__global__ void zero_scratch() {
    int idx = blockIdx.x * blockDim.x + threadIdx.x;
    int stride = gridDim.x * blockDim.x;
    for (int i = idx; i < NN * D; i += stride) g_agg[i] = 0.f;
    for (int i = idx; i < NN * 3; i += stride) g_aggx[i] = 0.f;
}

// ---------------- packed GEMM core ----------------
// s_in layout: [K][LDE] (edge index contiguous). Thread d owns output column d
// for all 32 edges as 16 packed f32x2 accumulators. One broadcast LDS.128
// feeds two FFMA2 (4 edges). Weight W[k*D+d] via coalesced LDG, duplicated once.
template <int K>
__device__ __forceinline__ void mlp2(const float* __restrict__ W, const float* s_in,
                                     float bias, u64* acc, int d) {
    u64 b2 = dup2(bias);
#pragma unroll
    for (int p = 0; p < 16; p++) acc[p] = b2;
#pragma unroll 2
    for (int k = 0; k < K; k += 4) {
        float w0 = W[(k + 0) * D + d];
        float w1 = W[(k + 1) * D + d];
        float w2 = W[(k + 2) * D + d];
        float w3 = W[(k + 3) * D + d];
        u64 wd0 = dup2(w0), wd1 = dup2(w1), wd2 = dup2(w2), wd3 = dup2(w3);
        const ulonglong2* r0 = (const ulonglong2*)(s_in + (k + 0) * LDE);
        const ulonglong2* r1 = (const ulonglong2*)(s_in + (k + 1) * LDE);
        const ulonglong2* r2 = (const ulonglong2*)(s_in + (k + 2) * LDE);
        const ulonglong2* r3 = (const ulonglong2*)(s_in + (k + 3) * LDE);
#pragma unroll
        for (int p = 0; p < 8; p++) {
            ulonglong2 v0 = r0[p];
            acc[2 * p]     = ffma2(v0.x, wd0, acc[2 * p]);
            acc[2 * p + 1] = ffma2(v0.y, wd0, acc[2 * p + 1]);
        }
#pragma unroll
        for (int p = 0; p < 8; p++) {
            ulonglong2 v1 = r1[p];
            acc[2 * p]     = ffma2(v1.x, wd1, acc[2 * p]);
            acc[2 * p + 1] = ffma2(v1.y, wd1, acc[2 * p + 1]);
        }
#pragma unroll
        for (int p = 0; p < 8; p++) {
            ulonglong2 v2 = r2[p];
            acc[2 * p]     = ffma2(v2.x, wd2, acc[2 * p]);
            acc[2 * p + 1] = ffma2(v2.y, wd2, acc[2 * p + 1]);
        }
#pragma unroll
        for (int p = 0; p < 8; p++) {
            ulonglong2 v3 = r3[p];
            acc[2 * p]     = ffma2(v3.x, wd3, acc[2 * p]);
            acc[2 * p + 1] = ffma2(v3.y, wd3, acc[2 * p + 1]);
        }
    }
}

// silu both halves of a packed pair and store as float2 (8B-aligned in [K][LDE])
__device__ __forceinline__ void silu_store2(float* dst, u64 a) {
    float2 v = unpk(a);
    float2 r;
    r.x = siluf(v.x);
    r.y = siluf(v.y);
    *(float2*)dst = r;
}

// ---------------- scalar FFMA GEMM (node kernels; tiny fraction of runtime) ----------------
template <int TEc, int K, int LD>
__device__ __forceinline__ void mlp_layer(const float* __restrict__ W,
                                          const float* s_in, float bias,
                                          float* acc, int d) {
#pragma unroll
    for (int e = 0; e < TEc; e++) acc[e] = bias;
#pragma unroll 2
    for (int k = 0; k < K; k += 4) {
        float w0 = W[(k + 0) * D + d];
        float w1 = W[(k + 1) * D + d];
        float w2 = W[(k + 2) * D + d];
        float w3 = W[(k + 3) * D + d];
#pragma unroll
        for (int e = 0; e < TEc; e++) {
            float4 v = *(const float4*)(s_in + e * LD + k);
            acc[e] = fmaf(v.x, w0, acc[e]);
            acc[e] = fmaf(v.y, w1, acc[e]);
            acc[e] = fmaf(v.z, w2, acc[e]);
            acc[e] = fmaf(v.w, w3, acc[e]);
        }
    }
}

// ---------------- node linear: g_hh = h @ W_lin + b ----------------
__global__ void node_lin(const float* __restrict__ h,
                         const float* __restrict__ Wlin,
                         const float* __restrict__ blin) {
    __shared__ __align__(16) float s_in[TN * D];
    int t = threadIdx.x;
    int r0 = blockIdx.x * TN;
    for (int e = 0; e < TN; e++) s_in[e * D + t] = h[(r0 + e) * D + t];
    __syncthreads();
    float acc[TN];
    mlp_layer<TN, 128, 128>(Wlin, s_in, blin[t], acc, t);
#pragma unroll
    for (int e = 0; e < TN; e++) g_hh[(r0 + e) * D + t] = acc[e];
}

// ---------------- edge message + attention kernel (packed f32x2) ----------------
__global__ void __launch_bounds__(128)
edge_msg(const float* __restrict__ x, const int* __restrict__ ei,
         const float* __restrict__ edge_mask,
         const float* __restrict__ edge_attr,
         const float* __restrict__ We2,
         const float* __restrict__ be1,
         const float* __restrict__ be2,
         const float* __restrict__ ba1,
         const float* __restrict__ Wa2,
         const float* __restrict__ ba2) {
    extern __shared__ float sm[];
    float* s_att = sm;                      // [260][LDE]  [hr | hc | e3 | 0]; reused for M1
    float* s_msg = s_att + 260 * LDE;       // [132][LDE]  [hc-hr | e3 | 0]
    float* s_m1  = s_msg + 132 * LDE;       // [128][LDE]  A1, then M1
    float* s_w2  = s_m1 + 128 * LDE;        // 128  Wa2
    float* s_as  = s_w2 + 128;              // TE   att scalar
    float* s_em  = s_as + TE;               // TE
    float* s_gp  = s_em + TE;               // TE*4 geo warp partials
    int*   s_row = (int*)(s_gp + TE * 4);   // TE
    int*   s_col = s_row + TE;              // TE

    int t = threadIdx.x, lane = t & 31, wid = t >> 5;
    int e0 = blockIdx.x * TE;

    if (t < TE) {
        s_row[t] = ei[e0 + t];
        s_col[t] = ei[NE + e0 + t];
        s_em[t]  = edge_mask[e0 + t];
    }
    s_w2[t] = Wa2[t];
    __syncthreads();

    // gather (transposed): thread t = feature index
    for (int e = 0; e < TE; e++) {
        float hr = g_hh[s_row[e] * D + t];
        float hc = g_hh[s_col[e] * D + t];
        s_att[t * LDE + e]         = hr;
        s_att[(128 + t) * LDE + e] = hc;
        float v = hc - hr;
        s_msg[t * LDE + e] = v;
        float p = v * v;
#pragma unroll
        for (int o = 16; o > 0; o >>= 1) p += __shfl_down_sync(0xffffffffu, p, o);
        if (lane == 0) s_gp[e * 4 + wid] = p;
    }
    __syncthreads();

    if (t < TE) {
        int e = t;
        float geo = sqrtf(s_gp[e * 4] + s_gp[e * 4 + 1] + s_gp[e * 4 + 2] +
                          s_gp[e * 4 + 3] + 1e-8f);
        int r = s_row[e], c = s_col[e];
        float dx = x[r * 3 + 0] - x[c * 3 + 0];
        float dy = x[r * 3 + 1] - x[c * 3 + 1];
        float dz = x[r * 3 + 2] - x[c * 3 + 2];
        float dist = sqrtf(dx * dx + dy * dy + dz * dz + 1e-8f);
        float ea = edge_attr[e0 + e];
        s_att[256 * LDE + e] = dist;
        s_att[257 * LDE + e] = ea;
        s_att[258 * LDE + e] = geo;
        s_att[259 * LDE + e] = 0.f;
        s_msg[128 * LDE + e] = dist;
        s_msg[129 * LDE + e] = ea;
        s_msg[130 * LDE + e] = geo;
        s_msg[131 * LDE + e] = 0.f;
        g_e3[(e0 + e) * 3 + 0] = dist;
        g_e3[(e0 + e) * 3 + 1] = ea;
        g_e3[(e0 + e) * 3 + 2] = geo;
    }
    __syncthreads();

    u64 acc[16];
    // A1 = silu(att_in @ Wa1 + ba1)  -> s_m1
    mlp2<260>(g_Wa1p, s_att, ba1[t], acc, t);
#pragma unroll
    for (int p = 0; p < 16; p++) silu_store2(s_m1 + t * LDE + 2 * p, acc[p]);
    __syncthreads();

    // att = sigmoid(A1 @ Wa2 + ba2) * edge_mask  (warp handles 8 edges)
    {
        float b2 = ba2[0];
        for (int i = 0; i < TE / 4; i++) {
            int e = wid * (TE / 4) + i;
            float s = s_m1[lane * LDE + e]        * s_w2[lane] +
                      s_m1[(lane + 32) * LDE + e] * s_w2[lane + 32] +
                      s_m1[(lane + 64) * LDE + e] * s_w2[lane + 64] +
                      s_m1[(lane + 96) * LDE + e] * s_w2[lane + 96];
#pragma unroll
            for (int o = 16; o > 0; o >>= 1) s += __shfl_down_sync(0xffffffffu, s, o);
            if (lane == 0) {
                float z = s + b2;
                s_as[e] = s_em[e] / (1.f + expf(-z));
            }
        }
    }
    __syncthreads();

    // M1 = silu(msg_in @ We1 + be1) -> overwrite s_m1 (A1 dead)
    mlp2<132>(g_We1p, s_msg, be1[t], acc, t);
    __syncthreads();  // all A1 reads done before overwrite
#pragma unroll
    for (int p = 0; p < 16; p++) silu_store2(s_m1 + t * LDE + 2 * p, acc[p]);
    __syncthreads();

    // msg = (M1 @ We2 + be2) * att ; scatter
    mlp2<128>(We2, s_m1, be2[t], acc, t);
#pragma unroll
    for (int p = 0; p < 16; p++) {
        float2 v = unpk(acc[p]);
        atomicAdd(&g_agg[s_row[2 * p] * D + t],     v.x * s_as[2 * p]);
        atomicAdd(&g_agg[s_row[2 * p + 1] * D + t], v.y * s_as[2 * p + 1]);
    }
}

// ---------------- node MLP + residual + LayerNorm + silu -> d_out ----------------
__global__ void node_mlp(const float* __restrict__ Wn1, const float* __restrict__ bn1,
                         const float* __restrict__ Wn2, const float* __restrict__ bn2,
                         const float* __restrict__ ln_g, const float* __restrict__ ln_b,
                         float* __restrict__ out_h) {
    __shared__ __align__(16) float s_a[TN * 128];
    __shared__ __align__(16) float s_t[TN * 128];
    __shared__ float s_mu[TN], s_rs[TN];
    int t = threadIdx.x, lane = t & 31, wid = t >> 5;
    int r0 = blockIdx.x * TN;

    for (int e = 0; e < TN; e++) s_a[e * 128 + t] = g_agg[(r0 + e) * D + t];
    __syncthreads();

    float acc[TN];
    mlp_layer<TN, 128, 128>(Wn1, s_a, bn1[t], acc, t);
#pragma unroll
    for (int e = 0; e < TN; e++) s_t[e * 128 + t] = siluf(acc[e]);
    __syncthreads();

    mlp_layer<TN, 128, 128>(Wn2, s_t, bn2[t], acc, t);
#pragma unroll
    for (int e = 0; e < TN; e++) {
        float v = g_hh[(r0 + e) * D + t] + acc[e];
        s_a[e * 128 + t] = v;
    }
    __syncthreads();

    for (int i = 0; i < TN / 4; i++) {
        int e = wid * (TN / 4) + i;
        float v0 = s_a[e * 128 + lane];
        float v1 = s_a[e * 128 + lane + 32];
        float v2 = s_a[e * 128 + lane + 64];
        float v3 = s_a[e * 128 + lane + 96];
        float s = v0 + v1 + v2 + v3;
        float q = v0 * v0 + v1 * v1 + v2 * v2 + v3 * v3;
#pragma unroll
        for (int o = 16; o > 0; o >>= 1) {
            s += __shfl_down_sync(0xffffffffu, s, o);
            q += __shfl_down_sync(0xffffffffu, q, o);
        }
        if (lane == 0) {
            float mu = s * (1.f / 128.f);
            float var = q * (1.f / 128.f) - mu * mu;
            s_mu[e] = mu;
            s_rs[e] = rsqrtf(var + 1e-5f);
        }
    }
    __syncthreads();

    float g = ln_g[t], bb = ln_b[t];
    for (int e = 0; e < TN; e++) {
        float v = (s_a[e * 128 + t] - s_mu[e]) * s_rs[e] * g + bb;
        out_h[(r0 + e) * D + t] = siluf(v);
    }
}

// ---------------- coord MLP + scatter (packed f32x2) ----------------
__global__ void __launch_bounds__(128)
edge_coord(const float* __restrict__ x, const int* __restrict__ ei,
           const float* __restrict__ edge_mask,
           const float* __restrict__ hh2,  // = d_out[0:N*D]
           const float* __restrict__ bc1,
           const float* __restrict__ Wc2,
           const float* __restrict__ bc2,
           const float* __restrict__ Wc3) {
    extern __shared__ float sm[];
    float* s_in = sm;                      // [260][LDE]; rows 0..127 reused for m2
    float* s_m1 = s_in + 260 * LDE;        // [128][LDE]
    float* s_w3 = s_m1 + 128 * LDE;        // 128
    float* s_mm = s_w3 + 128;              // TE
    float* s_em = s_mm + TE;               // TE
    int*   s_row = (int*)(s_em + TE);
    int*   s_col = s_row + TE;

    int t = threadIdx.x, lane = t & 31, wid = t >> 5;
    int e0 = blockIdx.x * TE;

    if (t < TE) {
        s_row[t] = ei[e0 + t];
        s_col[t] = ei[NE + e0 + t];
        s_em[t]  = edge_mask[e0 + t];
    }
    s_w3[t] = Wc3[t];
    __syncthreads();

    for (int e = 0; e < TE; e++) {
        s_in[t * LDE + e]         = hh2[s_row[e] * D + t];
        s_in[(128 + t) * LDE + e] = hh2[s_col[e] * D + t];
    }
    if (t < TE) {
        int e = t;
        s_in[256 * LDE + e] = g_e3[(e0 + e) * 3 + 0];
        s_in[257 * LDE + e] = g_e3[(e0 + e) * 3 + 1];
        s_in[258 * LDE + e] = g_e3[(e0 + e) * 3 + 2];
        s_in[259 * LDE + e] = 0.f;
    }
    __syncthreads();

    u64 acc[16];
    mlp2<260>(g_Wc1p, s_in, bc1[t], acc, t);
#pragma unroll
    for (int p = 0; p < 16; p++) silu_store2(s_m1 + t * LDE + 2 * p, acc[p]);
    __syncthreads();

    mlp2<128>(Wc2, s_m1, bc2[t], acc, t);
#pragma unroll
    for (int p = 0; p < 16; p++) silu_store2(s_in + t * LDE + 2 * p, acc[p]);  // m2 -> rows 0..127
    __syncthreads();

    // m = m2 @ Wc3 (no bias)
    for (int i = 0; i < TE / 4; i++) {
        int e = wid * (TE / 4) + i;
        float s = s_in[lane * LDE + e]        * s_w3[lane] +
                  s_in[(lane + 32) * LDE + e] * s_w3[lane + 32] +
                  s_in[(lane + 64) * LDE + e] * s_w3[lane + 64] +
                  s_in[(lane + 96) * LDE + e] * s_w3[lane + 96];
#pragma unroll
        for (int o = 16; o > 0; o >>= 1) s += __shfl_down_sync(0xffffffffu, s, o);
        if (lane == 0) s_mm[e] = s * s_em[e];
    }
    __syncthreads();

    if (t < TE) {
        int e = t;
        int r = s_row[e], c = s_col[e];
        float dx = x[r * 3 + 0] - x[c * 3 + 0];
        float dy = x[r * 3 + 1] - x[c * 3 + 1];
        float dz = x[r * 3 + 2] - x[c * 3 + 2];
        float dist = s_in[256 * LDE + e];   // rows 256+ untouched by m2 overwrite
        float inv = 1.f / (dist + 1.f);
        float m = s_mm[e];
        atomicAdd(&g_aggx[r * 3 + 0], dx * inv * m);
        atomicAdd(&g_aggx[r * 3 + 1], dy * inv * m);
        atomicAdd(&g_aggx[r * 3 + 2], dz * inv * m);
    }
}

__global__ void finalize_x(const float* __restrict__ x,
                           const float* __restrict__ node_mask,
                           float* __restrict__ out) {
    int i = blockIdx.x * blockDim.x + threadIdx.x;
    if (i < NN * 3) {
        out[i] = (x[i] + g_aggx[i] * (1.f / 100.f)) * node_mask[i / 3];
    }
}

// ---------------- launcher ----------------
extern "C" void kernel_launch(void* const* d_in, const int* in_sizes, int n_in,
                              void* d_out, int out_size) {
    const float* h         = (const float*)d_in[0];
    const float* x         = (const float*)d_in[1];
    const int*   ei        = (const int*)d_in[2];
    const float* node_mask = (const float*)d_in[3];
    const float* edge_mask = (const float*)d_in[4];
    const float* edge_attr = (const float*)d_in[5];
    const float* Wlin = (const float*)d_in[6];
    const float* blin = (const float*)d_in[7];
    const float* We1  = (const float*)d_in[8];
    const float* be1  = (const float*)d_in[9];
    const float* We2  = (const float*)d_in[10];
    const float* be2  = (const float*)d_in[11];
    const float* Wn1  = (const float*)d_in[12];
    const float* bn1  = (const float*)d_in[13];
    const float* Wn2  = (const float*)d_in[14];
    const float* bn2  = (const float*)d_in[15];
    const float* Wa1  = (const float*)d_in[16];
    const float* ba1  = (const float*)d_in[17];
    const float* Wa2  = (const float*)d_in[18];
    const float* ba2  = (const float*)d_in[19];
    const float* ln_g = (const float*)d_in[20];
    const float* ln_b = (const float*)d_in[21];
    const float* Wc1  = (const float*)d_in[22];
    const float* bc1  = (const float*)d_in[23];
    const float* Wc2  = (const float*)d_in[24];
    const float* bc2  = (const float*)d_in[25];
    const float* Wc3  = (const float*)d_in[26];
    float* out = (float*)d_out;

    const int SMEM_MSG = (260 * LDE + 132 * LDE + 128 * LDE + 128 + TE + TE + TE * 4) * 4
                         + 2 * TE * 4;
    const int SMEM_CRD = (260 * LDE + 128 * LDE + 128 + TE + TE) * 4 + 2 * TE * 4;

    cudaFuncSetAttribute(edge_msg, cudaFuncAttributeMaxDynamicSharedMemorySize, SMEM_MSG);
    cudaFuncSetAttribute(edge_coord, cudaFuncAttributeMaxDynamicSharedMemorySize, SMEM_CRD);

    prep_weights<<<dim3(131, 3), 256>>>(Wa1, We1, Wc1);
    zero_scratch<<<1024, 256>>>();
    node_lin<<<NN / TN, 128>>>(h, Wlin, blin);
    edge_msg<<<NE / TE, 128, SMEM_MSG>>>(x, ei, edge_mask, edge_attr,
                                         We2, be1, be2, ba1, Wa2, ba2);
    node_mlp<<<NN / TN, 128>>>(Wn1, bn1, Wn2, bn2, ln_g, ln_b, out);
    edge_coord<<<NE / TE, 128, SMEM_CRD>>>(x, ei, edge_mask, out, bc1, Wc2, bc2, Wc3);
    finalize_x<<<(NN * 3 + 255) / 256, 256>>>(x, node_mask, out + NN * D);
}